// round 6
// baseline (speedup 1.0000x reference)
#include <cuda_runtime.h>
#include <math.h>
#include <stdint.h>

#define B_ 4
#define L_ 2048
#define C_ 1024
#define H_ 16
#define D_ 64
#define M_ (B_ * L_)   // 8192 rows

// Scratch buffers (static device globals; no runtime allocation allowed)
__device__ float g_qkv[(size_t)M_ * 3 * C_];   // [8192, 3072]
__device__ float g_h[(size_t)M_ * C_];         // [8192, 1024]

// ---------------------------------------------------------------------------
// helpers: tf32 convert + m16n8k8 tf32 mma
// ---------------------------------------------------------------------------
__device__ __forceinline__ uint32_t f2tf(float f) {
    uint32_t r;
    asm("cvt.rna.tf32.f32 %0, %1;" : "=r"(r) : "f"(f));
    return r;
}

__device__ __forceinline__ void mma_tf32(float c[4],
    uint32_t a0, uint32_t a1, uint32_t a2, uint32_t a3,
    uint32_t b0, uint32_t b1)
{
    asm volatile(
        "mma.sync.aligned.m16n8k8.row.col.f32.tf32.tf32.f32 "
        "{%0,%1,%2,%3}, {%4,%5,%6,%7}, {%8,%9}, {%0,%1,%2,%3};"
        : "+f"(c[0]), "+f"(c[1]), "+f"(c[2]), "+f"(c[3])
        : "r"(a0), "r"(a1), "r"(a2), "r"(a3), "r"(b0), "r"(b1));
}

// ---------------------------------------------------------------------------
// TF32 tensor-core SGEMM (unchanged from round 2 — works, 243us combined)
// ---------------------------------------------------------------------------
#define GAP 20
#define GBP 136

__global__ __launch_bounds__(256) void gemm_tc_kernel(
    const float* __restrict__ A, const float* __restrict__ Bm,
    const float* __restrict__ bias, float* __restrict__ Cm,
    int M, int N, int K)
{
    __shared__ uint32_t As[128 * GAP];
    __shared__ uint32_t Bs[16 * GBP];

    const int tid  = threadIdx.x;
    const int warp = tid >> 5;
    const int lane = tid & 31;
    const int gid  = lane >> 2;
    const int t4   = lane & 3;

    const int wm = warp >> 1;
    const int wn = warp & 1;
    const int m0 = wm * 32;
    const int n0 = wn * 64;

    const int row0 = blockIdx.y * 128;
    const int col0 = blockIdx.x * 128;

    const int a_row = tid >> 1;
    const int a_k   = (tid & 1) * 8;
    const int b_row = tid >> 4;
    const int b_col = (tid & 15) * 8;

    float acc[2][8][4];
#pragma unroll
    for (int mt = 0; mt < 2; mt++)
#pragma unroll
        for (int nt = 0; nt < 8; nt++)
#pragma unroll
            for (int i = 0; i < 4; i++) acc[mt][nt][i] = 0.0f;

    const float* Aptr = A + (size_t)(row0 + a_row) * K;

    for (int k0 = 0; k0 < K; k0 += 16) {
        float4 av0 = *(const float4*)(Aptr + k0 + a_k);
        float4 av1 = *(const float4*)(Aptr + k0 + a_k + 4);
        {
            uint4 u0 = make_uint4(f2tf(av0.x), f2tf(av0.y), f2tf(av0.z), f2tf(av0.w));
            uint4 u1 = make_uint4(f2tf(av1.x), f2tf(av1.y), f2tf(av1.z), f2tf(av1.w));
            *(uint4*)&As[a_row * GAP + a_k]     = u0;
            *(uint4*)&As[a_row * GAP + a_k + 4] = u1;
        }
        float4 bv0 = *(const float4*)(Bm + (size_t)(k0 + b_row) * N + col0 + b_col);
        float4 bv1 = *(const float4*)(Bm + (size_t)(k0 + b_row) * N + col0 + b_col + 4);
        {
            uint4 u0 = make_uint4(f2tf(bv0.x), f2tf(bv0.y), f2tf(bv0.z), f2tf(bv0.w));
            uint4 u1 = make_uint4(f2tf(bv1.x), f2tf(bv1.y), f2tf(bv1.z), f2tf(bv1.w));
            *(uint4*)&Bs[b_row * GBP + b_col]     = u0;
            *(uint4*)&Bs[b_row * GBP + b_col + 4] = u1;
        }
        __syncthreads();

#pragma unroll
        for (int ks = 0; ks < 16; ks += 8) {
            uint32_t af[2][4];
#pragma unroll
            for (int mt = 0; mt < 2; mt++) {
                const int mbase = m0 + mt * 16;
                af[mt][0] = As[(mbase + gid)     * GAP + ks + t4];
                af[mt][1] = As[(mbase + gid + 8) * GAP + ks + t4];
                af[mt][2] = As[(mbase + gid)     * GAP + ks + t4 + 4];
                af[mt][3] = As[(mbase + gid + 8) * GAP + ks + t4 + 4];
            }
#pragma unroll
            for (int nt = 0; nt < 8; nt++) {
                uint32_t b0 = Bs[(ks + t4)     * GBP + n0 + nt * 8 + gid];
                uint32_t b1 = Bs[(ks + t4 + 4) * GBP + n0 + nt * 8 + gid];
                mma_tf32(acc[0][nt], af[0][0], af[0][1], af[0][2], af[0][3], b0, b1);
                mma_tf32(acc[1][nt], af[1][0], af[1][1], af[1][2], af[1][3], b0, b1);
            }
        }
        __syncthreads();
    }

#pragma unroll
    for (int mt = 0; mt < 2; mt++) {
        const int r0 = row0 + m0 + mt * 16 + gid;
#pragma unroll
        for (int nt = 0; nt < 8; nt++) {
            const int c = col0 + n0 + nt * 8 + t4 * 2;
            float bx = bias[c], by = bias[c + 1];
            *(float2*)(Cm + (size_t)r0 * N + c) =
                make_float2(acc[mt][nt][0] + bx, acc[mt][nt][1] + by);
            *(float2*)(Cm + (size_t)(r0 + 8) * N + c) =
                make_float2(acc[mt][nt][2] + bx, acc[mt][nt][3] + by);
        }
    }
}

// ---------------------------------------------------------------------------
// Per-head RMS norm (unchanged).
// ---------------------------------------------------------------------------
__global__ __launch_bounds__(256) void rmsnorm_kernel(
    float* __restrict__ qkv,
    const float* __restrict__ q_gamma, const float* __restrict__ k_gamma)
{
    const int warp = threadIdx.x >> 5;
    const int lane = threadIdx.x & 31;
    const int seg = blockIdx.x * 8 + warp;

    const int head = seg % H_;
    const int part = (seg / H_) & 1;
    const int row  = seg / (H_ * 2);

    float* ptr = qkv + ((size_t)row * 3 + part) * C_ + head * D_;
    float2 v = *(float2*)(ptr + lane * 2);
    float ss = v.x * v.x + v.y * v.y;
#pragma unroll
    for (int m = 16; m > 0; m >>= 1) ss += __shfl_xor_sync(0xffffffffu, ss, m);

    const float n = sqrtf(ss);
    const float scale = 8.0f / fmaxf(n, 1e-12f);
    const float* gamma = part ? k_gamma : q_gamma;
    float2 g = *(const float2*)(gamma + head * D_ + lane * 2);
    v.x *= scale * g.x;
    v.y *= scale * g.y;
    *(float2*)(ptr + lane * 2) = v;
}

// ---------------------------------------------------------------------------
// Flash attention, TF32 mma with FRAGMENT-PERMUTED smem layouts.
// CTA = (b, h, 64-row Q tile), 128 threads = 4 warps x 16 Q rows.
// K and V tiles are stored in smem already in mma B-fragment order:
//   KF[frag=nt*4+cp][lane] = uint4 {b0(ks=2cp), b1(ks=2cp), b0(2cp+1), b1(2cp+1)}
// so the whole B operand for 2 mmas is ONE conflict-free LDS.128.
// P is bounced per-warp through PF in A-fragment order (scatter write,
// LDS.128 read). Frag stride padded to 33 uint4 (132 words) for KF/VF to
// reduce write conflicts.
// Smem: KF 4224 + VF 4224 + union(QS 4352 staging | PF 4096) = 12800 words.
// ---------------------------------------------------------------------------
#define FRS 132                                 // frag stride in words
#define ATT_SMEM (12800 * 4)                    // 51200 bytes

__global__ __launch_bounds__(128) void attn_tc_kernel(
    const float* __restrict__ qkv, float* __restrict__ hout)
{
    extern __shared__ uint32_t sm[];
    uint32_t* KF = sm;                 // 32 frags * 132 = 4224
    uint32_t* VF = sm + 4224;          // 4224
    uint32_t* QS = sm + 8448;          // 4352 (staging, reused as PF)
    uint32_t* PF = sm + 8448;          // 4 warps * 1024

    const int tid  = threadIdx.x;
    const int warp = tid >> 5;
    const int lane = tid & 31;
    const int gid  = lane >> 2;
    const int t4   = lane & 3;

    const int b  = blockIdx.z;
    const int h  = blockIdx.y;
    const int l0 = blockIdx.x * 64;

    // loader mapping: 128 threads cover 64 rows x 64 cols
    const int lr = tid >> 1;            // 0..63
    const int lc = (tid & 1) * 32;      // 0 or 32

    // Q pre-scale: 1/sqrt(D) * log2(e)  (softmax done in exp2 domain)
    const float qscale = 0.125f * 1.44269504088896340736f;

    // ---- load Q tile (tf32, pre-scaled) into staging ----
    {
        const float* src = qkv + (((size_t)(b * L_ + l0 + lr) * 3 + 0) * C_) + h * D_;
#pragma unroll
        for (int u = 0; u < 8; u++) {
            float4 t = *(const float4*)(src + lc + u * 4);
            uint4 uq = make_uint4(f2tf(t.x * qscale), f2tf(t.y * qscale),
                                  f2tf(t.z * qscale), f2tf(t.w * qscale));
            *(uint4*)&QS[lr * 68 + lc + u * 4] = uq;
        }
    }
    __syncthreads();

    // ---- Q fragments to registers ----
    uint32_t qf[8][4];
    {
        const int mbase = warp * 16;
#pragma unroll
        for (int ks = 0; ks < 8; ks++) {
            qf[ks][0] = QS[(mbase + gid)     * 68 + ks * 8 + t4];
            qf[ks][1] = QS[(mbase + gid + 8) * 68 + ks * 8 + t4];
            qf[ks][2] = QS[(mbase + gid)     * 68 + ks * 8 + t4 + 4];
            qf[ks][3] = QS[(mbase + gid + 8) * 68 + ks * 8 + t4 + 4];
        }
    }
    // NOTE: first loop-top __syncthreads() guarantees all warps finished
    // reading QS before anyone writes PF (which aliases QS).

    float o[8][4];
#pragma unroll
    for (int nt = 0; nt < 8; nt++)
#pragma unroll
        for (int i = 0; i < 4; i++) o[nt][i] = 0.0f;

    float mrow0 = -1e30f, mrow1 = -1e30f;
    float lrow0 = 0.0f,   lrow1 = 0.0f;

    // precomputed loader constants
    const int ntK = lr >> 3, gidK = lr & 7;   // K: n = lr
    const int cpV = lr >> 4, wV = (lr >> 2) & 3, t4V = lr & 3;  // V: kk = lr

    for (int n0 = 0; n0 < L_; n0 += 64) {
        __syncthreads();   // prev iter's KF/VF reads (and initial QS reads) done

        // ---- load K, V tiles -> fragment-permuted smem ----
        {
            const float* ksrc = qkv + (((size_t)(b * L_ + n0 + lr) * 3 + 1) * C_) + h * D_;
            const float* vsrc = qkv + (((size_t)(b * L_ + n0 + lr) * 3 + 2) * C_) + h * D_;
#pragma unroll
            for (int u = 0; u < 8; u++) {
                const int c = lc + u * 4;
                float4 tk = *(const float4*)(ksrc + c);
                // K element (n=lr, k=c+j): frag=(ntK*4 + c>>4), lane=gidK*4+j, word=(c>>2)&3
                uint32_t* kd = &KF[(ntK * 4 + (c >> 4)) * FRS + gidK * 16 + ((c >> 2) & 3)];
                kd[0]  = f2tf(tk.x);
                kd[4]  = f2tf(tk.y);
                kd[8]  = f2tf(tk.z);
                kd[12] = f2tf(tk.w);

                float4 tv = *(const float4*)(vsrc + c);
                // V element (kk=lr, n=c+j): frag=((c>>3)*4 + cpV), lane=((c&7)+j)*4+t4V, word=wV
                uint32_t* vd = &VF[((c >> 3) * 4 + cpV) * FRS + ((c & 7) * 4 + t4V) * 4 + wV];
                vd[0]  = f2tf(tv.x);
                vd[16] = f2tf(tv.y);
                vd[32] = f2tf(tv.z);
                vd[48] = f2tf(tv.w);
            }
        }
        __syncthreads();

        // ---- S = Q K^T : 64 mmas, B-frags via 32 LDS.128 ----
        float s[8][4];
#pragma unroll
        for (int nt = 0; nt < 8; nt++)
#pragma unroll
            for (int i = 0; i < 4; i++) s[nt][i] = 0.0f;

#pragma unroll
        for (int nt = 0; nt < 8; nt++) {
            const uint32_t* kb = &KF[nt * 4 * FRS + lane * 4];
#pragma unroll
            for (int cp = 0; cp < 4; cp++) {
                uint4 f = *(const uint4*)(kb + cp * FRS);
                mma_tf32(s[nt], qf[2*cp][0],   qf[2*cp][1],   qf[2*cp][2],   qf[2*cp][3],   f.x, f.y);
                mma_tf32(s[nt], qf[2*cp+1][0], qf[2*cp+1][1], qf[2*cp+1][2], qf[2*cp+1][3], f.z, f.w);
            }
        }

        // ---- online softmax (log2 domain; rows gid / gid+8) ----
        float rmax0 = -1e30f, rmax1 = -1e30f;
#pragma unroll
        for (int nt = 0; nt < 8; nt++) {
            rmax0 = fmaxf(rmax0, fmaxf(s[nt][0], s[nt][1]));
            rmax1 = fmaxf(rmax1, fmaxf(s[nt][2], s[nt][3]));
        }
#pragma unroll
        for (int msk = 1; msk <= 2; msk <<= 1) {
            rmax0 = fmaxf(rmax0, __shfl_xor_sync(0xffffffffu, rmax0, msk));
            rmax1 = fmaxf(rmax1, __shfl_xor_sync(0xffffffffu, rmax1, msk));
        }

        const float mn0 = fmaxf(mrow0, rmax0);
        const float mn1 = fmaxf(mrow1, rmax1);
        const float corr0 = exp2f(mrow0 - mn0);
        const float corr1 = exp2f(mrow1 - mn1);
        mrow0 = mn0; mrow1 = mn1;

        // scatter P into per-warp A-fragment layout
        uint32_t* pw = &PF[warp * 1024 + gid * 16];
        const int cc = 2 * t4;                 // 0,2,4,6
        const int hi2 = (cc >= 4) ? 2 : 0;     // word base 0 or 2
        const int tr0 = cc & 3;
        const int tr1 = (cc + 1) & 3;

        float rs0 = 0.0f, rs1 = 0.0f;
#pragma unroll
        for (int nt = 0; nt < 8; nt++) {
            float p0 = exp2f(s[nt][0] - mn0);
            float p1 = exp2f(s[nt][1] - mn0);
            float p2 = exp2f(s[nt][2] - mn1);
            float p3 = exp2f(s[nt][3] - mn1);
            rs0 += p0 + p1;
            rs1 += p2 + p3;
            uint32_t* pb = pw + nt * 128;
            pb[tr0 * 4 + hi2]     = f2tf(p0);
            pb[tr1 * 4 + hi2]     = f2tf(p1);
            pb[tr0 * 4 + hi2 + 1] = f2tf(p2);
            pb[tr1 * 4 + hi2 + 1] = f2tf(p3);
        }
#pragma unroll
        for (int msk = 1; msk <= 2; msk <<= 1) {
            rs0 += __shfl_xor_sync(0xffffffffu, rs0, msk);
            rs1 += __shfl_xor_sync(0xffffffffu, rs1, msk);
        }
        lrow0 = lrow0 * corr0 + rs0;
        lrow1 = lrow1 * corr1 + rs1;

#pragma unroll
        for (int nt = 0; nt < 8; nt++) {
            o[nt][0] *= corr0; o[nt][1] *= corr0;
            o[nt][2] *= corr1; o[nt][3] *= corr1;
        }
        __syncwarp();   // PF is per-warp private

        // ---- O += P V : P A-frags via 8 LDS.128, V via 32 LDS.128 ----
        uint32_t pf[8][4];
        {
            const uint32_t* pb = &PF[warp * 1024 + lane * 4];
#pragma unroll
            for (int ch = 0; ch < 8; ch++)
                *(uint4*)&pf[ch][0] = *(const uint4*)(pb + ch * 128);
        }
#pragma unroll
        for (int nt = 0; nt < 8; nt++) {
            const uint32_t* vb = &VF[nt * 4 * FRS + lane * 4];
#pragma unroll
            for (int cp = 0; cp < 4; cp++) {
                uint4 g = *(const uint4*)(vb + cp * FRS);
                mma_tf32(o[nt], pf[2*cp][0],   pf[2*cp][1],   pf[2*cp][2],   pf[2*cp][3],   g.x, g.y);
                mma_tf32(o[nt], pf[2*cp+1][0], pf[2*cp+1][1], pf[2*cp+1][2], pf[2*cp+1][3], g.z, g.w);
            }
        }
    }

    // ---- write normalized output ----
    const float inv0 = 1.0f / lrow0;
    const float inv1 = 1.0f / lrow1;
    const int r0 = b * L_ + l0 + warp * 16 + gid;
#pragma unroll
    for (int nt = 0; nt < 8; nt++) {
        const int c = h * D_ + nt * 8 + 2 * t4;
        *(float2*)(hout + (size_t)r0 * C_ + c) =
            make_float2(o[nt][0] * inv0, o[nt][1] * inv0);
        *(float2*)(hout + (size_t)(r0 + 8) * C_ + c) =
            make_float2(o[nt][2] * inv1, o[nt][3] * inv1);
    }
}

// ---------------------------------------------------------------------------
// kernel_launch
// ---------------------------------------------------------------------------
extern "C" void kernel_launch(void* const* d_in, const int* in_sizes, int n_in,
                              void* d_out, int out_size)
{
    const float* x     = (const float*)d_in[0];
    const float* Wqkv  = (const float*)d_in[1];
    const float* bqkv  = (const float*)d_in[2];
    const float* qg    = (const float*)d_in[3];
    const float* kg    = (const float*)d_in[4];
    const float* Wout  = (const float*)d_in[5];
    const float* bout  = (const float*)d_in[6];
    float* out = (float*)d_out;

    float *qkv, *hbuf;
    cudaGetSymbolAddress((void**)&qkv, g_qkv);
    cudaGetSymbolAddress((void**)&hbuf, g_h);

    // 1) QKV projection
    {
        dim3 grid(3 * C_ / 128, M_ / 128);
        gemm_tc_kernel<<<grid, 256>>>(x, Wqkv, bqkv, qkv, M_, 3 * C_, C_);
    }

    // 2) RMS norm on Q and K heads (in place)
    {
        const int nseg = M_ * 2 * H_;
        rmsnorm_kernel<<<nseg / 8, 256>>>(qkv, qg, kg);
    }

    // 3) Attention
    {
        static int attr_set = 0;
        if (!attr_set) {
            cudaFuncSetAttribute(attn_tc_kernel,
                                 cudaFuncAttributeMaxDynamicSharedMemorySize,
                                 ATT_SMEM);
            attr_set = 1;
        }
        dim3 grid(L_ / 64, H_, B_);
        attn_tc_kernel<<<grid, 128, ATT_SMEM>>>(qkv, hbuf);
    }

    // 4) Output projection
    {
        dim3 grid(C_ / 128, M_ / 128);
        gemm_tc_kernel<<<grid, 256>>>(hbuf, Wout, bout, out, M_, C_, C_);
    }
}

// round 7
// speedup vs baseline: 1.4851x; 1.4851x over previous
#include <cuda_runtime.h>
#include <math.h>
#include <stdint.h>

#define B_ 4
#define L_ 2048
#define C_ 1024
#define H_ 16
#define D_ 64
#define M_ (B_ * L_)   // 8192 rows

// Scratch buffers (static device globals; no runtime allocation allowed)
__device__ float g_qkv[(size_t)M_ * 3 * C_];   // [8192, 3072]
__device__ float g_h[(size_t)M_ * C_];         // [8192, 1024]

// ---------------------------------------------------------------------------
// helpers: tf32 convert + m16n8k8 tf32 mma
// ---------------------------------------------------------------------------
__device__ __forceinline__ uint32_t f2tf(float f) {
    uint32_t r;
    asm("cvt.rna.tf32.f32 %0, %1;" : "=r"(r) : "f"(f));
    return r;
}

__device__ __forceinline__ void mma_tf32(float c[4],
    uint32_t a0, uint32_t a1, uint32_t a2, uint32_t a3,
    uint32_t b0, uint32_t b1)
{
    asm volatile(
        "mma.sync.aligned.m16n8k8.row.col.f32.tf32.tf32.f32 "
        "{%0,%1,%2,%3}, {%4,%5,%6,%7}, {%8,%9}, {%0,%1,%2,%3};"
        : "+f"(c[0]), "+f"(c[1]), "+f"(c[2]), "+f"(c[3])
        : "r"(a0), "r"(a1), "r"(a2), "r"(a3), "r"(b0), "r"(b1));
}

// ---------------------------------------------------------------------------
// TF32 tensor-core SGEMM (unchanged — proven)
// ---------------------------------------------------------------------------
#define GAP 20
#define GBP 136

__global__ __launch_bounds__(256) void gemm_tc_kernel(
    const float* __restrict__ A, const float* __restrict__ Bm,
    const float* __restrict__ bias, float* __restrict__ Cm,
    int M, int N, int K)
{
    __shared__ uint32_t As[128 * GAP];
    __shared__ uint32_t Bs[16 * GBP];

    const int tid  = threadIdx.x;
    const int warp = tid >> 5;
    const int lane = tid & 31;
    const int gid  = lane >> 2;
    const int t4   = lane & 3;

    const int wm = warp >> 1;
    const int wn = warp & 1;
    const int m0 = wm * 32;
    const int n0 = wn * 64;

    const int row0 = blockIdx.y * 128;
    const int col0 = blockIdx.x * 128;

    const int a_row = tid >> 1;
    const int a_k   = (tid & 1) * 8;
    const int b_row = tid >> 4;
    const int b_col = (tid & 15) * 8;

    float acc[2][8][4];
#pragma unroll
    for (int mt = 0; mt < 2; mt++)
#pragma unroll
        for (int nt = 0; nt < 8; nt++)
#pragma unroll
            for (int i = 0; i < 4; i++) acc[mt][nt][i] = 0.0f;

    const float* Aptr = A + (size_t)(row0 + a_row) * K;

    for (int k0 = 0; k0 < K; k0 += 16) {
        float4 av0 = *(const float4*)(Aptr + k0 + a_k);
        float4 av1 = *(const float4*)(Aptr + k0 + a_k + 4);
        {
            uint4 u0 = make_uint4(f2tf(av0.x), f2tf(av0.y), f2tf(av0.z), f2tf(av0.w));
            uint4 u1 = make_uint4(f2tf(av1.x), f2tf(av1.y), f2tf(av1.z), f2tf(av1.w));
            *(uint4*)&As[a_row * GAP + a_k]     = u0;
            *(uint4*)&As[a_row * GAP + a_k + 4] = u1;
        }
        float4 bv0 = *(const float4*)(Bm + (size_t)(k0 + b_row) * N + col0 + b_col);
        float4 bv1 = *(const float4*)(Bm + (size_t)(k0 + b_row) * N + col0 + b_col + 4);
        {
            uint4 u0 = make_uint4(f2tf(bv0.x), f2tf(bv0.y), f2tf(bv0.z), f2tf(bv0.w));
            uint4 u1 = make_uint4(f2tf(bv1.x), f2tf(bv1.y), f2tf(bv1.z), f2tf(bv1.w));
            *(uint4*)&Bs[b_row * GBP + b_col]     = u0;
            *(uint4*)&Bs[b_row * GBP + b_col + 4] = u1;
        }
        __syncthreads();

#pragma unroll
        for (int ks = 0; ks < 16; ks += 8) {
            uint32_t af[2][4];
#pragma unroll
            for (int mt = 0; mt < 2; mt++) {
                const int mbase = m0 + mt * 16;
                af[mt][0] = As[(mbase + gid)     * GAP + ks + t4];
                af[mt][1] = As[(mbase + gid + 8) * GAP + ks + t4];
                af[mt][2] = As[(mbase + gid)     * GAP + ks + t4 + 4];
                af[mt][3] = As[(mbase + gid + 8) * GAP + ks + t4 + 4];
            }
#pragma unroll
            for (int nt = 0; nt < 8; nt++) {
                uint32_t b0 = Bs[(ks + t4)     * GBP + n0 + nt * 8 + gid];
                uint32_t b1 = Bs[(ks + t4 + 4) * GBP + n0 + nt * 8 + gid];
                mma_tf32(acc[0][nt], af[0][0], af[0][1], af[0][2], af[0][3], b0, b1);
                mma_tf32(acc[1][nt], af[1][0], af[1][1], af[1][2], af[1][3], b0, b1);
            }
        }
        __syncthreads();
    }

#pragma unroll
    for (int mt = 0; mt < 2; mt++) {
        const int r0 = row0 + m0 + mt * 16 + gid;
#pragma unroll
        for (int nt = 0; nt < 8; nt++) {
            const int c = col0 + n0 + nt * 8 + t4 * 2;
            float bx = bias[c], by = bias[c + 1];
            *(float2*)(Cm + (size_t)r0 * N + c) =
                make_float2(acc[mt][nt][0] + bx, acc[mt][nt][1] + by);
            *(float2*)(Cm + (size_t)(r0 + 8) * N + c) =
                make_float2(acc[mt][nt][2] + bx, acc[mt][nt][3] + by);
        }
    }
}

// ---------------------------------------------------------------------------
// Per-head RMS norm (unchanged).
// ---------------------------------------------------------------------------
__global__ __launch_bounds__(256) void rmsnorm_kernel(
    float* __restrict__ qkv,
    const float* __restrict__ q_gamma, const float* __restrict__ k_gamma)
{
    const int warp = threadIdx.x >> 5;
    const int lane = threadIdx.x & 31;
    const int seg = blockIdx.x * 8 + warp;

    const int head = seg % H_;
    const int part = (seg / H_) & 1;
    const int row  = seg / (H_ * 2);

    float* ptr = qkv + ((size_t)row * 3 + part) * C_ + head * D_;
    float2 v = *(float2*)(ptr + lane * 2);
    float ss = v.x * v.x + v.y * v.y;
#pragma unroll
    for (int m = 16; m > 0; m >>= 1) ss += __shfl_xor_sync(0xffffffffu, ss, m);

    const float n = sqrtf(ss);
    const float scale = 8.0f / fmaxf(n, 1e-12f);
    const float* gamma = part ? k_gamma : q_gamma;
    float2 g = *(const float2*)(gamma + head * D_ + lane * 2);
    v.x *= scale * g.x;
    v.y *= scale * g.y;
    *(float2*)(ptr + lane * 2) = v;
}

// ---------------------------------------------------------------------------
// Flash attention, TF32 mma.  Round-2 layouts, 128-row Q tile / 8 warps.
// CTA = (b, h, 128-row Q tile), 256 threads. Warp w owns Q rows w*16..+15.
// Per 64-key tile: S = Q K^T (Q frags in regs), online softmax (exp2 domain,
// Q pre-scaled by 1/sqrt(D)*log2e), P bounced per-warp through PS (row
// layout, pitch 68), O += P V.
// Smem words: Ks 64*84=5376 | Vs 64*72=4608 | QS/PS union 128*68=8704
//   total 18688 words = 74752 B  -> 2 CTAs/SM (16 warps = 4/SMSP).
// ---------------------------------------------------------------------------
#define KP 84
#define VP 72
#define QPP 68
#define ATT_SMEM (18688 * 4)   // 74752 bytes

__global__ __launch_bounds__(256, 2) void attn_tc_kernel(
    const float* __restrict__ qkv, float* __restrict__ hout)
{
    extern __shared__ uint32_t sm[];
    uint32_t* Ks = sm;                 // 5376
    uint32_t* Vs = sm + 5376;          // 4608
    uint32_t* QS = sm + 9984;          // 8704 (Q staging, reused as PS)
    uint32_t* PS = QS;

    const int tid  = threadIdx.x;
    const int warp = tid >> 5;
    const int lane = tid & 31;
    const int gid  = lane >> 2;
    const int t4   = lane & 3;

    const int b  = blockIdx.z;
    const int h  = blockIdx.y;
    const int l0 = blockIdx.x * 128;

    // Q loader: 256 threads cover 128 rows x 64 cols
    const int qlr = tid >> 1;           // 0..127
    const int qlc = (tid & 1) * 32;     // 0 or 32
    // K/V loader: 256 threads cover 64 rows x 64 cols
    const int lr = tid >> 2;            // 0..63
    const int lc = (tid & 3) * 16;      // 0,16,32,48

    // Q pre-scale: 1/sqrt(D) * log2(e)  (softmax in exp2 domain)
    const float qscale = 0.125f * 1.44269504088896340736f;

    // ---- load Q tile (tf32, pre-scaled) into staging ----
    {
        const float* src = qkv + (((size_t)(b * L_ + l0 + qlr) * 3 + 0) * C_) + h * D_;
#pragma unroll
        for (int u = 0; u < 8; u++) {
            float4 t = *(const float4*)(src + qlc + u * 4);
            uint4 uq = make_uint4(f2tf(t.x * qscale), f2tf(t.y * qscale),
                                  f2tf(t.z * qscale), f2tf(t.w * qscale));
            *(uint4*)&QS[qlr * QPP + qlc + u * 4] = uq;
        }
    }
    __syncthreads();

    // ---- Q fragments to registers (invariant across key tiles) ----
    uint32_t qf[8][4];
    {
        const int mbase = warp * 16;
#pragma unroll
        for (int ks = 0; ks < 8; ks++) {
            qf[ks][0] = QS[(mbase + gid)     * QPP + ks * 8 + t4];
            qf[ks][1] = QS[(mbase + gid + 8) * QPP + ks * 8 + t4];
            qf[ks][2] = QS[(mbase + gid)     * QPP + ks * 8 + t4 + 4];
            qf[ks][3] = QS[(mbase + gid + 8) * QPP + ks * 8 + t4 + 4];
        }
    }
    // First loop-top __syncthreads() separates these QS reads from the first
    // PS writes (PS aliases QS).

    float o[8][4];
#pragma unroll
    for (int nt = 0; nt < 8; nt++)
#pragma unroll
        for (int i = 0; i < 4; i++) o[nt][i] = 0.0f;

    float mrow0 = -1e30f, mrow1 = -1e30f;
    float lrow0 = 0.0f,   lrow1 = 0.0f;

    for (int n0 = 0; n0 < L_; n0 += 64) {
        __syncthreads();   // prev iter's Ks/Vs reads (and initial QS reads) done

        // ---- load K, V tiles (tf32) ----
        {
            const float* ksrc = qkv + (((size_t)(b * L_ + n0 + lr) * 3 + 1) * C_) + h * D_;
            const float* vsrc = qkv + (((size_t)(b * L_ + n0 + lr) * 3 + 2) * C_) + h * D_;
#pragma unroll
            for (int u = 0; u < 4; u++) {
                float4 tk = *(const float4*)(ksrc + lc + u * 4);
                float4 tv = *(const float4*)(vsrc + lc + u * 4);
                *(uint4*)&Ks[lr * KP + lc + u * 4] =
                    make_uint4(f2tf(tk.x), f2tf(tk.y), f2tf(tk.z), f2tf(tk.w));
                *(uint4*)&Vs[lr * VP + lc + u * 4] =
                    make_uint4(f2tf(tv.x), f2tf(tv.y), f2tf(tv.z), f2tf(tv.w));
            }
        }
        __syncthreads();

        // ---- S = Q K^T (64-key tile), per-warp 16x64 ----
        float s[8][4];
#pragma unroll
        for (int nt = 0; nt < 8; nt++)
#pragma unroll
            for (int i = 0; i < 4; i++) s[nt][i] = 0.0f;

#pragma unroll
        for (int ks = 0; ks < 8; ks++) {
#pragma unroll
            for (int nt = 0; nt < 8; nt++) {
                uint32_t b0 = Ks[(nt * 8 + gid) * KP + ks * 8 + t4];
                uint32_t b1 = Ks[(nt * 8 + gid) * KP + ks * 8 + t4 + 4];
                mma_tf32(s[nt], qf[ks][0], qf[ks][1], qf[ks][2], qf[ks][3], b0, b1);
            }
        }

        // ---- online softmax (exp2 domain; rows gid / gid+8) ----
        float rmax0 = -1e30f, rmax1 = -1e30f;
#pragma unroll
        for (int nt = 0; nt < 8; nt++) {
            rmax0 = fmaxf(rmax0, fmaxf(s[nt][0], s[nt][1]));
            rmax1 = fmaxf(rmax1, fmaxf(s[nt][2], s[nt][3]));
        }
#pragma unroll
        for (int msk = 1; msk <= 2; msk <<= 1) {
            rmax0 = fmaxf(rmax0, __shfl_xor_sync(0xffffffffu, rmax0, msk));
            rmax1 = fmaxf(rmax1, __shfl_xor_sync(0xffffffffu, rmax1, msk));
        }

        const float mn0 = fmaxf(mrow0, rmax0);
        const float mn1 = fmaxf(mrow1, rmax1);
        const float corr0 = exp2f(mrow0 - mn0);
        const float corr1 = exp2f(mrow1 - mn1);
        mrow0 = mn0; mrow1 = mn1;

        const int prow0 = warp * 16 + gid;
        float rs0 = 0.0f, rs1 = 0.0f;
#pragma unroll
        for (int nt = 0; nt < 8; nt++) {
            float p0 = exp2f(s[nt][0] - mn0);
            float p1 = exp2f(s[nt][1] - mn0);
            float p2 = exp2f(s[nt][2] - mn1);
            float p3 = exp2f(s[nt][3] - mn1);
            rs0 += p0 + p1;
            rs1 += p2 + p3;
            const int cc = nt * 8 + 2 * t4;
            PS[prow0 * QPP + cc]           = f2tf(p0);
            PS[prow0 * QPP + cc + 1]       = f2tf(p1);
            PS[(prow0 + 8) * QPP + cc]     = f2tf(p2);
            PS[(prow0 + 8) * QPP + cc + 1] = f2tf(p3);
        }
#pragma unroll
        for (int msk = 1; msk <= 2; msk <<= 1) {
            rs0 += __shfl_xor_sync(0xffffffffu, rs0, msk);
            rs1 += __shfl_xor_sync(0xffffffffu, rs1, msk);
        }
        lrow0 = lrow0 * corr0 + rs0;
        lrow1 = lrow1 * corr1 + rs1;

#pragma unroll
        for (int nt = 0; nt < 8; nt++) {
            o[nt][0] *= corr0; o[nt][1] *= corr0;
            o[nt][2] *= corr1; o[nt][3] *= corr1;
        }
        __syncwarp();   // PS rows are per-warp private

        // ---- O += P V ----
#pragma unroll
        for (int ks = 0; ks < 8; ks++) {
            uint32_t pf0 = PS[(warp * 16 + gid)     * QPP + ks * 8 + t4];
            uint32_t pf1 = PS[(warp * 16 + gid + 8) * QPP + ks * 8 + t4];
            uint32_t pf2 = PS[(warp * 16 + gid)     * QPP + ks * 8 + t4 + 4];
            uint32_t pf3 = PS[(warp * 16 + gid + 8) * QPP + ks * 8 + t4 + 4];
#pragma unroll
            for (int nt = 0; nt < 8; nt++) {
                uint32_t b0 = Vs[(ks * 8 + t4)     * VP + nt * 8 + gid];
                uint32_t b1 = Vs[(ks * 8 + t4 + 4) * VP + nt * 8 + gid];
                mma_tf32(o[nt], pf0, pf1, pf2, pf3, b0, b1);
            }
        }
    }

    // ---- write normalized output ----
    const float inv0 = 1.0f / lrow0;
    const float inv1 = 1.0f / lrow1;
    const int r0 = b * L_ + l0 + warp * 16 + gid;
#pragma unroll
    for (int nt = 0; nt < 8; nt++) {
        const int c = h * D_ + nt * 8 + 2 * t4;
        *(float2*)(hout + (size_t)r0 * C_ + c) =
            make_float2(o[nt][0] * inv0, o[nt][1] * inv0);
        *(float2*)(hout + (size_t)(r0 + 8) * C_ + c) =
            make_float2(o[nt][2] * inv1, o[nt][3] * inv1);
    }
}

// ---------------------------------------------------------------------------
// kernel_launch
// ---------------------------------------------------------------------------
extern "C" void kernel_launch(void* const* d_in, const int* in_sizes, int n_in,
                              void* d_out, int out_size)
{
    const float* x     = (const float*)d_in[0];
    const float* Wqkv  = (const float*)d_in[1];
    const float* bqkv  = (const float*)d_in[2];
    const float* qg    = (const float*)d_in[3];
    const float* kg    = (const float*)d_in[4];
    const float* Wout  = (const float*)d_in[5];
    const float* bout  = (const float*)d_in[6];
    float* out = (float*)d_out;

    float *qkv, *hbuf;
    cudaGetSymbolAddress((void**)&qkv, g_qkv);
    cudaGetSymbolAddress((void**)&hbuf, g_h);

    // 1) QKV projection
    {
        dim3 grid(3 * C_ / 128, M_ / 128);
        gemm_tc_kernel<<<grid, 256>>>(x, Wqkv, bqkv, qkv, M_, 3 * C_, C_);
    }

    // 2) RMS norm on Q and K heads (in place)
    {
        const int nseg = M_ * 2 * H_;
        rmsnorm_kernel<<<nseg / 8, 256>>>(qkv, qg, kg);
    }

    // 3) Attention
    {
        static int attr_set = 0;
        if (!attr_set) {
            cudaFuncSetAttribute(attn_tc_kernel,
                                 cudaFuncAttributeMaxDynamicSharedMemorySize,
                                 ATT_SMEM);
            attr_set = 1;
        }
        dim3 grid(L_ / 128, H_, B_);
        attn_tc_kernel<<<grid, 256, ATT_SMEM>>>(qkv, hbuf);
    }

    // 4) Output projection
    {
        dim3 grid(C_ / 128, M_ / 128);
        gemm_tc_kernel<<<grid, 256>>>(hbuf, Wout, bout, out, M_, C_, C_);
    }
}

// round 11
// speedup vs baseline: 1.5057x; 1.0139x over previous
#include <cuda_runtime.h>
#include <math.h>
#include <stdint.h>

#define B_ 4
#define L_ 2048
#define C_ 1024
#define H_ 16
#define D_ 64
#define M_ (B_ * L_)   // 8192 rows

// Scratch buffers (static device globals; no runtime allocation allowed)
__device__ float g_qkv[(size_t)M_ * 3 * C_];   // [8192, 3072]
__device__ float g_h[(size_t)M_ * C_];         // [8192, 1024]

// ---------------------------------------------------------------------------
// helpers: tf32 convert + m16n8k8 tf32 mma + cp.async
// ---------------------------------------------------------------------------
__device__ __forceinline__ uint32_t f2tf(float f) {
    uint32_t r;
    asm("cvt.rna.tf32.f32 %0, %1;" : "=r"(r) : "f"(f));
    return r;
}

__device__ __forceinline__ float f2tf_f(float f) {
    uint32_t r = f2tf(f);
    return __uint_as_float(r);
}

__device__ __forceinline__ void mma_tf32(float c[4],
    uint32_t a0, uint32_t a1, uint32_t a2, uint32_t a3,
    uint32_t b0, uint32_t b1)
{
    asm volatile(
        "mma.sync.aligned.m16n8k8.row.col.f32.tf32.tf32.f32 "
        "{%0,%1,%2,%3}, {%4,%5,%6,%7}, {%8,%9}, {%0,%1,%2,%3};"
        : "+f"(c[0]), "+f"(c[1]), "+f"(c[2]), "+f"(c[3])
        : "r"(a0), "r"(a1), "r"(a2), "r"(a3), "r"(b0), "r"(b1));
}

__device__ __forceinline__ void cp_async16(uint32_t smem_addr, const void* gptr) {
    asm volatile("cp.async.cg.shared.global [%0], [%1], 16;"
                 :: "r"(smem_addr), "l"(gptr));
}
__device__ __forceinline__ void cp_commit() {
    asm volatile("cp.async.commit_group;");
}
__device__ __forceinline__ void cp_wait_all() {
    asm volatile("cp.async.wait_group 0;");
}

// ---------------------------------------------------------------------------
// TF32 tensor-core SGEMM (unchanged — proven)
// ---------------------------------------------------------------------------
#define GAP 20
#define GBP 136

__global__ __launch_bounds__(256) void gemm_tc_kernel(
    const float* __restrict__ A, const float* __restrict__ Bm,
    const float* __restrict__ bias, float* __restrict__ Cm,
    int M, int N, int K)
{
    __shared__ uint32_t As[128 * GAP];
    __shared__ uint32_t Bs[16 * GBP];

    const int tid  = threadIdx.x;
    const int warp = tid >> 5;
    const int lane = tid & 31;
    const int gid  = lane >> 2;
    const int t4   = lane & 3;

    const int wm = warp >> 1;
    const int wn = warp & 1;
    const int m0 = wm * 32;
    const int n0 = wn * 64;

    const int row0 = blockIdx.y * 128;
    const int col0 = blockIdx.x * 128;

    const int a_row = tid >> 1;
    const int a_k   = (tid & 1) * 8;
    const int b_row = tid >> 4;
    const int b_col = (tid & 15) * 8;

    float acc[2][8][4];
#pragma unroll
    for (int mt = 0; mt < 2; mt++)
#pragma unroll
        for (int nt = 0; nt < 8; nt++)
#pragma unroll
            for (int i = 0; i < 4; i++) acc[mt][nt][i] = 0.0f;

    const float* Aptr = A + (size_t)(row0 + a_row) * K;

    for (int k0 = 0; k0 < K; k0 += 16) {
        float4 av0 = *(const float4*)(Aptr + k0 + a_k);
        float4 av1 = *(const float4*)(Aptr + k0 + a_k + 4);
        {
            uint4 u0 = make_uint4(f2tf(av0.x), f2tf(av0.y), f2tf(av0.z), f2tf(av0.w));
            uint4 u1 = make_uint4(f2tf(av1.x), f2tf(av1.y), f2tf(av1.z), f2tf(av1.w));
            *(uint4*)&As[a_row * GAP + a_k]     = u0;
            *(uint4*)&As[a_row * GAP + a_k + 4] = u1;
        }
        float4 bv0 = *(const float4*)(Bm + (size_t)(k0 + b_row) * N + col0 + b_col);
        float4 bv1 = *(const float4*)(Bm + (size_t)(k0 + b_row) * N + col0 + b_col + 4);
        {
            uint4 u0 = make_uint4(f2tf(bv0.x), f2tf(bv0.y), f2tf(bv0.z), f2tf(bv0.w));
            uint4 u1 = make_uint4(f2tf(bv1.x), f2tf(bv1.y), f2tf(bv1.z), f2tf(bv1.w));
            *(uint4*)&Bs[b_row * GBP + b_col]     = u0;
            *(uint4*)&Bs[b_row * GBP + b_col + 4] = u1;
        }
        __syncthreads();

#pragma unroll
        for (int ks = 0; ks < 16; ks += 8) {
            uint32_t af[2][4];
#pragma unroll
            for (int mt = 0; mt < 2; mt++) {
                const int mbase = m0 + mt * 16;
                af[mt][0] = As[(mbase + gid)     * GAP + ks + t4];
                af[mt][1] = As[(mbase + gid + 8) * GAP + ks + t4];
                af[mt][2] = As[(mbase + gid)     * GAP + ks + t4 + 4];
                af[mt][3] = As[(mbase + gid + 8) * GAP + ks + t4 + 4];
            }
#pragma unroll
            for (int nt = 0; nt < 8; nt++) {
                uint32_t b0 = Bs[(ks + t4)     * GBP + n0 + nt * 8 + gid];
                uint32_t b1 = Bs[(ks + t4 + 4) * GBP + n0 + nt * 8 + gid];
                mma_tf32(acc[0][nt], af[0][0], af[0][1], af[0][2], af[0][3], b0, b1);
                mma_tf32(acc[1][nt], af[1][0], af[1][1], af[1][2], af[1][3], b0, b1);
            }
        }
        __syncthreads();
    }

#pragma unroll
    for (int mt = 0; mt < 2; mt++) {
        const int r0 = row0 + m0 + mt * 16 + gid;
#pragma unroll
        for (int nt = 0; nt < 8; nt++) {
            const int c = col0 + n0 + nt * 8 + t4 * 2;
            float bx = bias[c], by = bias[c + 1];
            *(float2*)(Cm + (size_t)r0 * N + c) =
                make_float2(acc[mt][nt][0] + bx, acc[mt][nt][1] + by);
            *(float2*)(Cm + (size_t)(r0 + 8) * N + c) =
                make_float2(acc[mt][nt][2] + bx, acc[mt][nt][3] + by);
        }
    }
}

// ---------------------------------------------------------------------------
// Per-head RMS norm on Q and K, in place, writing tf32-ROUNDED values so the
// attention kernel can cp.async them directly (numerically identical to
// converting at load time — f2tf is idempotent).
// ---------------------------------------------------------------------------
__global__ __launch_bounds__(256) void rmsnorm_kernel(
    float* __restrict__ qkv,
    const float* __restrict__ q_gamma, const float* __restrict__ k_gamma)
{
    const int warp = threadIdx.x >> 5;
    const int lane = threadIdx.x & 31;
    const int seg = blockIdx.x * 8 + warp;

    const int head = seg % H_;
    const int part = (seg / H_) & 1;
    const int row  = seg / (H_ * 2);

    float* ptr = qkv + ((size_t)row * 3 + part) * C_ + head * D_;
    float2 v = *(float2*)(ptr + lane * 2);
    float ss = v.x * v.x + v.y * v.y;
#pragma unroll
    for (int m = 16; m > 0; m >>= 1) ss += __shfl_xor_sync(0xffffffffu, ss, m);

    const float n = sqrtf(ss);
    const float scale = 8.0f / fmaxf(n, 1e-12f);
    const float* gamma = part ? k_gamma : q_gamma;
    float2 g = *(const float2*)(gamma + head * D_ + lane * 2);
    v.x = f2tf_f(v.x * scale * g.x);
    v.y = f2tf_f(v.y * scale * g.y);
    *(float2*)(ptr + lane * 2) = v;
}

// ---------------------------------------------------------------------------
// Round V slice of qkv to tf32 in place (producer-side convert for cp.async).
// ---------------------------------------------------------------------------
__global__ __launch_bounds__(256) void round_v_kernel(float* __restrict__ qkv)
{
    const int idx = blockIdx.x * 256 + threadIdx.x;     // float4 index
    const int row = idx >> 8;                            // C_/4 = 256 per row
    const int col = (idx & 255) * 4;
    float* p = qkv + ((size_t)row * 3 + 2) * C_ + col;
    float4 t = *(float4*)p;
    t.x = f2tf_f(t.x); t.y = f2tf_f(t.y);
    t.z = f2tf_f(t.z); t.w = f2tf_f(t.w);
    *(float4*)p = t;
}

// ---------------------------------------------------------------------------
// Flash attention, TF32 mma, cp.async double-buffered K/V pipeline.
// CTA = (b, h, 128-row Q tile), 256 threads = 8 warps x 16 Q rows.
// K/V tiles (64 keys) stream GMEM->SMEM via cp.async.cg, prefetched one tile
// ahead into a 2-stage buffer -> ONE barrier pair per iteration, GMEM latency
// hidden behind compute, no cvt/STS in the consumer path (pre-rounded tf32).
// Smem words/stage: Ks 64*76=4864 | Vs 64*72=4608  (9472/stage)
//   + QS/PS union 128*68=8704  -> total 27648 words = 110592 B -> 2 CTAs/SM.
// ---------------------------------------------------------------------------
#define KP2 76
#define VP2 72
#define KVW (64 * KP2 + 64 * VP2)    // 9472 words per stage
#define QPP 68
#define ATT_SMEM ((2 * KVW + 128 * QPP) * 4)   // 110592 bytes

__global__ __launch_bounds__(256, 2) void attn_tc_kernel(
    const float* __restrict__ qkv, float* __restrict__ hout)
{
    extern __shared__ uint32_t sm[];
    uint32_t* QS = sm + 2 * KVW;       // Q staging, reused as PS
    uint32_t* PS = QS;

    const uint32_t smem_u32 = (uint32_t)__cvta_generic_to_shared(sm);

    const int tid  = threadIdx.x;
    const int warp = tid >> 5;
    const int lane = tid & 31;
    const int gid  = lane >> 2;
    const int t4   = lane & 3;

    const int b  = blockIdx.z;
    const int h  = blockIdx.y;
    const int l0 = blockIdx.x * 128;

    // Q loader: 256 threads cover 128 rows x 64 cols
    const int qlr = tid >> 1;
    const int qlc = (tid & 1) * 32;
    // K/V loader: 256 threads cover 64 rows x 64 cols (16 cols each)
    const int lr = tid >> 2;            // 0..63
    const int lc = (tid & 3) * 16;      // 0,16,32,48

    const float qscale = 0.125f * 1.44269504088896340736f;  // 1/sqrt(D)*log2e

    // base gmem pointers for this (b,h)
    const float* kbase = qkv + (((size_t)(b * L_ + lr) * 3 + 1) * C_) + h * D_ + lc;
    const float* vbase = qkv + (((size_t)(b * L_ + lr) * 3 + 2) * C_) + h * D_ + lc;
    const size_t rowstep = (size_t)3 * C_;   // advance one key row

    // ---- prologue: issue cp.async for tile 0 into stage 0 ----
    {
        const uint32_t kdst = smem_u32 + (0 * KVW + lr * KP2 + lc) * 4;
        const uint32_t vdst = smem_u32 + (0 * KVW + 64 * KP2 + lr * VP2 + lc) * 4;
#pragma unroll
        for (int u = 0; u < 4; u++) {
            cp_async16(kdst + u * 16, kbase + u * 4);
            cp_async16(vdst + u * 16, vbase + u * 4);
        }
        cp_commit();
    }

    // ---- load Q tile (pre-rounded tf32; apply qscale) into staging ----
    {
        const float* src = qkv + (((size_t)(b * L_ + l0 + qlr) * 3 + 0) * C_) + h * D_;
#pragma unroll
        for (int u = 0; u < 8; u++) {
            float4 t = *(const float4*)(src + qlc + u * 4);
            uint4 uq = make_uint4(f2tf(t.x * qscale), f2tf(t.y * qscale),
                                  f2tf(t.z * qscale), f2tf(t.w * qscale));
            *(uint4*)&QS[qlr * QPP + qlc + u * 4] = uq;
        }
    }
    __syncthreads();

    // ---- Q fragments to registers ----
    uint32_t qf[8][4];
    {
        const int mbase = warp * 16;
#pragma unroll
        for (int ks = 0; ks < 8; ks++) {
            qf[ks][0] = QS[(mbase + gid)     * QPP + ks * 8 + t4];
            qf[ks][1] = QS[(mbase + gid + 8) * QPP + ks * 8 + t4];
            qf[ks][2] = QS[(mbase + gid)     * QPP + ks * 8 + t4 + 4];
            qf[ks][3] = QS[(mbase + gid + 8) * QPP + ks * 8 + t4 + 4];
        }
    }
    // The first loop-top __syncthreads separates these QS reads from the
    // first PS writes (PS aliases QS).

    float o[8][4];
#pragma unroll
    for (int nt = 0; nt < 8; nt++)
#pragma unroll
        for (int i = 0; i < 4; i++) o[nt][i] = 0.0f;

    float mrow0 = -1e30f, mrow1 = -1e30f;
    float lrow0 = 0.0f,   lrow1 = 0.0f;

    for (int it = 0; it < L_ / 64; it++) {
        const int p = it & 1;
        uint32_t* Ks = sm + p * KVW;
        uint32_t* Vs = sm + p * KVW + 64 * KP2;

        // tile `it` has landed; all warps done with stage p^1 reads
        cp_wait_all();
        __syncthreads();

        // prefetch tile it+1 into stage p^1 (safe: everyone passed the barrier)
        if (it + 1 < L_ / 64) {
            const size_t off = (size_t)(it + 1) * 64 * rowstep;
            const uint32_t s1 = (p ^ 1) * KVW;
            const uint32_t kdst = smem_u32 + (s1 + lr * KP2 + lc) * 4;
            const uint32_t vdst = smem_u32 + (s1 + 64 * KP2 + lr * VP2 + lc) * 4;
#pragma unroll
            for (int u = 0; u < 4; u++) {
                cp_async16(kdst + u * 16, kbase + off + u * 4);
                cp_async16(vdst + u * 16, vbase + off + u * 4);
            }
            cp_commit();
        }

        // ---- S = Q K^T (64-key tile), per-warp 16x64 ----
        float s[8][4];
#pragma unroll
        for (int nt = 0; nt < 8; nt++)
#pragma unroll
            for (int i = 0; i < 4; i++) s[nt][i] = 0.0f;

#pragma unroll
        for (int ks = 0; ks < 8; ks++) {
#pragma unroll
            for (int nt = 0; nt < 8; nt++) {
                uint32_t b0 = Ks[(nt * 8 + gid) * KP2 + ks * 8 + t4];
                uint32_t b1 = Ks[(nt * 8 + gid) * KP2 + ks * 8 + t4 + 4];
                mma_tf32(s[nt], qf[ks][0], qf[ks][1], qf[ks][2], qf[ks][3], b0, b1);
            }
        }

        // ---- online softmax (exp2 domain; rows gid / gid+8) ----
        float rmax0 = -1e30f, rmax1 = -1e30f;
#pragma unroll
        for (int nt = 0; nt < 8; nt++) {
            rmax0 = fmaxf(rmax0, fmaxf(s[nt][0], s[nt][1]));
            rmax1 = fmaxf(rmax1, fmaxf(s[nt][2], s[nt][3]));
        }
#pragma unroll
        for (int msk = 1; msk <= 2; msk <<= 1) {
            rmax0 = fmaxf(rmax0, __shfl_xor_sync(0xffffffffu, rmax0, msk));
            rmax1 = fmaxf(rmax1, __shfl_xor_sync(0xffffffffu, rmax1, msk));
        }

        const float mn0 = fmaxf(mrow0, rmax0);
        const float mn1 = fmaxf(mrow1, rmax1);
        const float corr0 = exp2f(mrow0 - mn0);
        const float corr1 = exp2f(mrow1 - mn1);
        mrow0 = mn0; mrow1 = mn1;

        const int prow0 = warp * 16 + gid;
        float rs0 = 0.0f, rs1 = 0.0f;
#pragma unroll
        for (int nt = 0; nt < 8; nt++) {
            float p0 = exp2f(s[nt][0] - mn0);
            float p1 = exp2f(s[nt][1] - mn0);
            float p2 = exp2f(s[nt][2] - mn1);
            float p3 = exp2f(s[nt][3] - mn1);
            rs0 += p0 + p1;
            rs1 += p2 + p3;
            const int cc = nt * 8 + 2 * t4;
            PS[prow0 * QPP + cc]           = f2tf(p0);
            PS[prow0 * QPP + cc + 1]       = f2tf(p1);
            PS[(prow0 + 8) * QPP + cc]     = f2tf(p2);
            PS[(prow0 + 8) * QPP + cc + 1] = f2tf(p3);
        }
#pragma unroll
        for (int msk = 1; msk <= 2; msk <<= 1) {
            rs0 += __shfl_xor_sync(0xffffffffu, rs0, msk);
            rs1 += __shfl_xor_sync(0xffffffffu, rs1, msk);
        }
        lrow0 = lrow0 * corr0 + rs0;
        lrow1 = lrow1 * corr1 + rs1;

#pragma unroll
        for (int nt = 0; nt < 8; nt++) {
            o[nt][0] *= corr0; o[nt][1] *= corr0;
            o[nt][2] *= corr1; o[nt][3] *= corr1;
        }
        __syncwarp();   // PS rows are per-warp private

        // ---- O += P V ----
#pragma unroll
        for (int ks = 0; ks < 8; ks++) {
            uint32_t pf0 = PS[(warp * 16 + gid)     * QPP + ks * 8 + t4];
            uint32_t pf1 = PS[(warp * 16 + gid + 8) * QPP + ks * 8 + t4];
            uint32_t pf2 = PS[(warp * 16 + gid)     * QPP + ks * 8 + t4 + 4];
            uint32_t pf3 = PS[(warp * 16 + gid + 8) * QPP + ks * 8 + t4 + 4];
#pragma unroll
            for (int nt = 0; nt < 8; nt++) {
                uint32_t b0 = Vs[(ks * 8 + t4)     * VP2 + nt * 8 + gid];
                uint32_t b1 = Vs[(ks * 8 + t4 + 4) * VP2 + nt * 8 + gid];
                mma_tf32(o[nt], pf0, pf1, pf2, pf3, b0, b1);
            }
        }
        __syncthreads();   // all reads of stage p done before next prefetch overwrites it
    }

    // ---- write normalized output ----
    const float inv0 = 1.0f / lrow0;
    const float inv1 = 1.0f / lrow1;
    const int r0 = b * L_ + l0 + warp * 16 + gid;
#pragma unroll
    for (int nt = 0; nt < 8; nt++) {
        const int c = h * D_ + nt * 8 + 2 * t4;
        *(float2*)(hout + (size_t)r0 * C_ + c) =
            make_float2(o[nt][0] * inv0, o[nt][1] * inv0);
        *(float2*)(hout + (size_t)(r0 + 8) * C_ + c) =
            make_float2(o[nt][2] * inv1, o[nt][3] * inv1);
    }
}

// ---------------------------------------------------------------------------
// kernel_launch
// ---------------------------------------------------------------------------
extern "C" void kernel_launch(void* const* d_in, const int* in_sizes, int n_in,
                              void* d_out, int out_size)
{
    const float* x     = (const float*)d_in[0];
    const float* Wqkv  = (const float*)d_in[1];
    const float* bqkv  = (const float*)d_in[2];
    const float* qg    = (const float*)d_in[3];
    const float* kg    = (const float*)d_in[4];
    const float* Wout  = (const float*)d_in[5];
    const float* bout  = (const float*)d_in[6];
    float* out = (float*)d_out;

    float *qkv, *hbuf;
    cudaGetSymbolAddress((void**)&qkv, g_qkv);
    cudaGetSymbolAddress((void**)&hbuf, g_h);

    // raise smem limit for the attention kernel (idempotent, capture-safe)
    cudaFuncSetAttribute(attn_tc_kernel,
                         cudaFuncAttributeMaxDynamicSharedMemorySize, ATT_SMEM);

    // 1) QKV projection
    {
        dim3 grid(3 * C_ / 128, M_ / 128);
        gemm_tc_kernel<<<grid, 256>>>(x, Wqkv, bqkv, qkv, M_, 3 * C_, C_);
    }

    // 2) RMS norm on Q,K (writes tf32-rounded) + round V to tf32
    {
        const int nseg = M_ * 2 * H_;
        rmsnorm_kernel<<<nseg / 8, 256>>>(qkv, qg, kg);
        round_v_kernel<<<(M_ * C_ / 4) / 256, 256>>>(qkv);
    }

    // 3) Attention (cp.async pipelined)
    {
        dim3 grid(L_ / 128, H_, B_);
        attn_tc_kernel<<<grid, 256, ATT_SMEM>>>(qkv, hbuf);
    }

    // 4) Output projection
    {
        dim3 grid(C_ / 128, M_ / 128);
        gemm_tc_kernel<<<grid, 256>>>(hbuf, Wout, bout, out, M_, C_, C_);
    }
}